// round 7
// baseline (speedup 1.0000x reference)
#include <cuda_runtime.h>
#include <cuda_fp16.h>
#include <cstdint>
#include <math.h>

// Problem constants
constexpr int NB  = 8;     // batch
constexpr int NC  = 128;   // channels
constexpr int NP  = 2048;  // points
constexpr int NH  = 4;     // heads
constexpr int NCH = 512;   // c*h
constexpr int NZ  = NB * NH;  // 32 (b,h) slices

// ---------------- scratch (static device globals; no allocation) -------------
__device__ __align__(1024) float  g_scale[NC];
__device__ __align__(1024) float  g_shift[NC];
__device__ __align__(1024) __half g_xh [NB * NP * NC];         // x half [b][p][c]
__device__ __align__(1024) __half g_wqk[1024 * 128];           // [(q|k)(h,c')][c]
__device__ __align__(1024) __half g_wv [512 * 128];            // [(h,c')][c]
__device__ __align__(1024) __half g_wo [128 * 512];            // [c][(h,c')]
__device__ __align__(1024) float  g_bqk[1024];
__device__ __align__(1024) float  g_bvv[512];
__device__ __align__(1024) __half g_qkh[NB * NP * 1024];       // [b][p][q(h,c')|k(h,c')]
__device__ __align__(1024) __half g_vh [NB * NCH * NP];        // [b][(h,c')][p]
__device__ __align__(1024) __half g_ath[NB * NP * NCH];        // [b][p][(h,c')]

// =================== PTX helpers =============================================
__device__ __forceinline__ uint32_t smem_u32(const void* p) {
    uint32_t a;
    asm("{ .reg .u64 t; cvta.to.shared.u64 t, %1; cvt.u32.u64 %0, t; }" : "=r"(a) : "l"(p));
    return a;
}
__device__ __forceinline__ void cp16(uint32_t s, const void* g) {
    asm volatile("cp.async.cg.shared.global [%0], [%1], 16;" :: "r"(s), "l"(g));
}
__device__ __forceinline__ void cp_commit() { asm volatile("cp.async.commit_group;"); }
__device__ __forceinline__ void cp_wait0()  { asm volatile("cp.async.wait_group 0;"); }
__device__ __forceinline__ void cp_wait1()  { asm volatile("cp.async.wait_group 1;"); }
__device__ __forceinline__ void ldsm4(uint32_t* r, uint32_t addr) {
    asm volatile("ldmatrix.sync.aligned.m8n8.x4.shared.b16 {%0,%1,%2,%3}, [%4];"
                 : "=r"(r[0]), "=r"(r[1]), "=r"(r[2]), "=r"(r[3]) : "r"(addr));
}
__device__ __forceinline__ void mma16816(float* d, const uint32_t* a, const uint32_t* b) {
    asm volatile(
        "mma.sync.aligned.m16n8k16.row.col.f32.f16.f16.f32 "
        "{%0,%1,%2,%3}, {%4,%5,%6,%7}, {%8,%9}, {%0,%1,%2,%3};"
        : "+f"(d[0]), "+f"(d[1]), "+f"(d[2]), "+f"(d[3])
        : "r"(a[0]), "r"(a[1]), "r"(a[2]), "r"(a[3]), "r"(b[0]), "r"(b[1]));
}
__device__ __forceinline__ float ex2(float x) {
    float y;
    asm("ex2.approx.f32 %0, %1;" : "=f"(y) : "f"(x));
    return y;
}

// ---------------- HMMA GEMM: C[M][N] = alpha * A[M][K] * B[N][K]^T -----------
// CTA tile 128x128, 8 warps of 32x64, K in chunks of 128, double-buffered.
// EPI: 0 = alpha only; 1 = + bias[n]; 2 = + bias[m]; 3 = plain; 4 = + bias[m] + res
constexpr int LDS_H       = 136;                  // halves per smem row (pad 8)
constexpr int TILE_HALVES = 128 * LDS_H;
constexpr int BUF_BYTES   = 2 * TILE_HALVES * 2;  // A+B one buffer = 69632 B

template <typename OutT, int EPI>
__global__ __launch_bounds__(256) void hgemm_nt(
    const __half* __restrict__ A, const __half* __restrict__ B, OutT* __restrict__ C,
    const float* __restrict__ bias, const float* __restrict__ res,
    int kchunks, int lda, int ldb, int ldc,
    long sAo, long sAi, long sBo, long sBi, long sCo, long sCi,
    int zH, float alpha)
{
    extern __shared__ __half smh[];
    const uint32_t sbase = smem_u32(smh);

    const int z  = blockIdx.z;
    const int zo = z / zH, zi = z % zH;
    const int m0 = blockIdx.y * 128, n0 = blockIdx.x * 128;
    A += (size_t)zo * sAo + (size_t)zi * sAi + (size_t)m0 * lda;
    B += (size_t)zo * sBo + (size_t)zi * sBi + (size_t)n0 * ldb;
    const size_t coff = (size_t)zo * sCo + (size_t)zi * sCi + (size_t)m0 * ldc + n0;
    C += coff;
    const float* R = res;
    if (EPI == 4) R += coff;

    const int tid  = threadIdx.x;
    const int lane = tid & 31;
    const int wid  = tid >> 5;
    const int wm   = (wid & 3) * 32;    // warp m offset
    const int wn   = (wid >> 2) * 64;   // warp n offset

    auto loadc = [&](int buf, int kofs) {
        const uint32_t ab = sbase + (uint32_t)buf * BUF_BYTES;
        const uint32_t bb = ab + TILE_HALVES * 2;
#pragma unroll
        for (int i = 0; i < 8; i++) {
            int idx = i * 256 + tid;
            int row = idx >> 4;
            int col = (idx & 15) * 8;     // halves
            cp16(ab + (uint32_t)(row * LDS_H + col) * 2, A + (size_t)row * lda + kofs + col);
            cp16(bb + (uint32_t)(row * LDS_H + col) * 2, B + (size_t)row * ldb + kofs + col);
        }
        cp_commit();
    };

    float acc[2][8][4] = {};

    loadc(0, 0);
    for (int kc = 0; kc < kchunks; kc++) {
        if (kc + 1 < kchunks) { loadc((kc + 1) & 1, (kc + 1) * 128); cp_wait1(); }
        else                  { cp_wait0(); }
        __syncthreads();

        const uint32_t ab = sbase + (uint32_t)(kc & 1) * BUF_BYTES;
        const uint32_t bb = ab + TILE_HALVES * 2;

#pragma unroll
        for (int ks = 0; ks < 8; ks++) {
            const int k0 = ks * 16;
            uint32_t af[2][4];
#pragma unroll
            for (int mf = 0; mf < 2; mf++) {
                int m  = wm + mf * 16 + (lane & 7) + ((lane >> 3) & 1) * 8;
                int kk = k0 + (lane >> 4) * 8;
                ldsm4(af[mf], ab + (uint32_t)(m * LDS_H + kk) * 2);
            }
            uint32_t bf[8][2];
#pragma unroll
            for (int p = 0; p < 4; p++) {
                int nrow = wn + p * 16 + ((lane >> 4) & 1) * 8 + (lane & 7);
                int kk   = k0 + ((lane >> 3) & 1) * 8;
                uint32_t r[4];
                ldsm4(r, bb + (uint32_t)(nrow * LDS_H + kk) * 2);
                bf[2 * p][0] = r[0]; bf[2 * p][1] = r[1];
                bf[2 * p + 1][0] = r[2]; bf[2 * p + 1][1] = r[3];
            }
#pragma unroll
            for (int mf = 0; mf < 2; mf++)
#pragma unroll
                for (int nf = 0; nf < 8; nf++)
                    mma16816(acc[mf][nf], af[mf], bf[nf]);
        }
        __syncthreads();
    }

    // epilogue: m16n8 c-frag: rows (lane>>2, +8), cols (lane&3)*2
#pragma unroll
    for (int mf = 0; mf < 2; mf++) {
#pragma unroll
        for (int nf = 0; nf < 8; nf++) {
            int m = wm + mf * 16 + (lane >> 2);
            int n = wn + nf * 8 + (lane & 3) * 2;
            float v0 = acc[mf][nf][0] * alpha, v1 = acc[mf][nf][1] * alpha;
            float v2 = acc[mf][nf][2] * alpha, v3 = acc[mf][nf][3] * alpha;
            if (EPI == 1) {
                float b0 = bias[n0 + n], b1 = bias[n0 + n + 1];
                v0 += b0; v1 += b1; v2 += b0; v3 += b1;
            }
            if (EPI == 2 || EPI == 4) {
                float bm0 = bias[m0 + m], bm1 = bias[m0 + m + 8];
                v0 += bm0; v1 += bm0; v2 += bm1; v3 += bm1;
            }
            if (EPI == 4) {
                float2 r0 = *(const float2*)(R + (size_t)m * ldc + n);
                float2 r1 = *(const float2*)(R + (size_t)(m + 8) * ldc + n);
                v0 += r0.x; v1 += r0.y; v2 += r1.x; v3 += r1.y;
            }
            if (sizeof(OutT) == 2) {
                *(__half2*)((__half*)C + (size_t)m * ldc + n)       = __floats2half2_rn(v0, v1);
                *(__half2*)((__half*)C + (size_t)(m + 8) * ldc + n) = __floats2half2_rn(v2, v3);
            } else {
                *(float2*)((float*)C + (size_t)m * ldc + n)       = make_float2(v0, v1);
                *(float2*)((float*)C + (size_t)(m + 8) * ldc + n) = make_float2(v2, v3);
            }
        }
    }
}

// ---------------- fused flash attention (no-max softmax, 2 CTAs/SM) ------------
// 128 threads / 4 warps, 64-query-row tile, single-buffered K/V tiles.
// Two co-resident CTAs per SM overlap: one loads/exps while the other MMAs.
// Q is pre-scaled by alpha*log2(e) at projection time, so p = exp2(S) directly.
constexpr int FTILE  = 128 * LDS_H;                  // K or V tile halves
constexpr int FQTILE = 64 * LDS_H;                   // Q tile halves
constexpr int FSMEM  = (FQTILE + 2 * FTILE) * 2;     // 87040 bytes

__global__ __launch_bounds__(128, 2) void flash_k() {
    extern __shared__ __half fsm[];
    const uint32_t sb = smem_u32(fsm);
    const int tid = threadIdx.x, lane = tid & 31, wid = tid >> 5;
    const int i0 = blockIdx.x * 64;
    const int z  = blockIdx.y;
    const int b  = z >> 2, h = z & 3;

    const __half* Qg = g_qkh + (size_t)b * NP * 1024 + (size_t)i0 * 1024 + h * 128;
    const __half* Kg = g_qkh + (size_t)b * NP * 1024 + 512 + h * 128;
    const __half* Vg = g_vh  + (size_t)b * NCH * NP + (size_t)h * 128 * NP;

    const uint32_t kb = sb + FQTILE * 2;
    const uint32_t vb = kb + FTILE * 2;

    // Q tile (64 rows) -> smem
#pragma unroll
    for (int i = 0; i < 8; i++) {
        int idx = i * 128 + tid, row = idx >> 4, col = (idx & 15) * 8;
        cp16(sb + (uint32_t)(row * LDS_H + col) * 2, Qg + (size_t)row * 1024 + col);
    }
    auto loadKV = [&](int j0) {
#pragma unroll
        for (int i = 0; i < 16; i++) {
            int idx = i * 128 + tid, row = idx >> 4, col = (idx & 15) * 8;
            cp16(kb + (uint32_t)(row * LDS_H + col) * 2, Kg + (size_t)(j0 + row) * 1024 + col);
            cp16(vb + (uint32_t)(row * LDS_H + col) * 2, Vg + (size_t)row * NP + j0 + col);
        }
        cp_commit();
    };
    loadKV(0);

    const int wm = wid * 16;
    uint32_t qf[8][4];
    float oacc[16][4] = {};
    float l0 = 0.f, l1 = 0.f;

    for (int kc = 0; kc < 16; kc++) {
        cp_wait0();
        __syncthreads();
        if (kc == 0) {
#pragma unroll
            for (int ks = 0; ks < 8; ks++)
                ldsm4(qf[ks], sb + (uint32_t)((wm + (lane & 15)) * LDS_H
                                              + ks * 16 + (lane >> 4) * 8) * 2);
        }

        // ---- S = Q K^T (Q pre-scaled; raw exp2 args) ----
        float sacc[16][4] = {};
#pragma unroll
        for (int ks = 0; ks < 8; ks++) {
            uint32_t bf[16][2];
#pragma unroll
            for (int p = 0; p < 8; p++) {
                int nrow = p * 16 + ((lane >> 4) & 1) * 8 + (lane & 7);
                int kk   = ks * 16 + ((lane >> 3) & 1) * 8;
                uint32_t r[4];
                ldsm4(r, kb + (uint32_t)(nrow * LDS_H + kk) * 2);
                bf[2 * p][0] = r[0]; bf[2 * p][1] = r[1];
                bf[2 * p + 1][0] = r[2]; bf[2 * p + 1][1] = r[3];
            }
#pragma unroll
            for (int nf = 0; nf < 16; nf++) mma16816(sacc[nf], qf[ks], bf[nf]);
        }

        // ---- p = exp2(S); accumulate l; pack half into frag slots ----
#pragma unroll
        for (int nf = 0; nf < 16; nf++) {
            float p0 = ex2(sacc[nf][0]);
            float p1 = ex2(sacc[nf][1]);
            float p2 = ex2(sacc[nf][2]);
            float p3 = ex2(sacc[nf][3]);
            l0 += p0 + p1; l1 += p2 + p3;
            __half2 h01 = __floats2half2_rn(p0, p1);
            __half2 h23 = __floats2half2_rn(p2, p3);
            sacc[nf][0] = __uint_as_float(*(uint32_t*)&h01);
            sacc[nf][1] = __uint_as_float(*(uint32_t*)&h23);
        }

        // ---- O += P V^T (P c-frags reused as A-frags) ----
#pragma unroll
        for (int ks = 0; ks < 8; ks++) {
            uint32_t af[4];
            af[0] = __float_as_uint(sacc[2 * ks][0]);
            af[1] = __float_as_uint(sacc[2 * ks][1]);
            af[2] = __float_as_uint(sacc[2 * ks + 1][0]);
            af[3] = __float_as_uint(sacc[2 * ks + 1][1]);
            uint32_t bfv[16][2];
#pragma unroll
            for (int p = 0; p < 8; p++) {
                int nrow = p * 16 + ((lane >> 4) & 1) * 8 + (lane & 7);
                int kk   = ks * 16 + ((lane >> 3) & 1) * 8;
                uint32_t r[4];
                ldsm4(r, vb + (uint32_t)(nrow * LDS_H + kk) * 2);
                bfv[2 * p][0] = r[0]; bfv[2 * p][1] = r[1];
                bfv[2 * p + 1][0] = r[2]; bfv[2 * p + 1][1] = r[3];
            }
#pragma unroll
            for (int nf = 0; nf < 16; nf++) mma16816(oacc[nf], af, bfv[nf]);
        }
        __syncthreads();                       // all warps done reading K/V
        if (kc + 1 < 16) loadKV((kc + 1) * 128);
    }

    // ---- epilogue: reduce l across quad, normalize, write att ----
    l0 += __shfl_xor_sync(0xffffffffu, l0, 1);
    l0 += __shfl_xor_sync(0xffffffffu, l0, 2);
    l1 += __shfl_xor_sync(0xffffffffu, l1, 1);
    l1 += __shfl_xor_sync(0xffffffffu, l1, 2);
    float inv0 = 1.f / l0, inv1 = 1.f / l1;
    const int row0 = i0 + wm + (lane >> 2);
    __half* ob = g_ath + (size_t)b * NP * NCH;
#pragma unroll
    for (int nf = 0; nf < 16; nf++) {
        int col = h * 128 + nf * 8 + (lane & 3) * 2;
        *(__half2*)(ob + (size_t)row0 * NCH + col) =
            __floats2half2_rn(oacc[nf][0] * inv0, oacc[nf][1] * inv0);
        *(__half2*)(ob + (size_t)(row0 + 8) * NCH + col) =
            __floats2half2_rn(oacc[nf][2] * inv1, oacc[nf][3] * inv1);
    }
}

// ---------------- batchnorm statistics ---------------------------------------
__global__ __launch_bounds__(256) void bn_stats_k(const float* __restrict__ in,
                                                  const float* __restrict__ gamma,
                                                  const float* __restrict__ beta) {
    const int c = blockIdx.x;
    const int t = threadIdx.x;
    float s = 0.f, ss = 0.f;
    for (int idx = t; idx < NB * NP; idx += 256) {
        int b = idx >> 11;
        int p = idx & (NP - 1);
        float v = in[(size_t)b * NC * NP + (size_t)c * NP + p];
        s += v; ss += v * v;
    }
    __shared__ float r1[256], r2[256];
    r1[t] = s; r2[t] = ss;
    __syncthreads();
    for (int off = 128; off > 0; off >>= 1) {
        if (t < off) { r1[t] += r1[t + off]; r2[t] += r2[t + off]; }
        __syncthreads();
    }
    if (t == 0) {
        const float invN = 1.f / (NB * NP);
        float mean = r1[0] * invN;
        float var  = r2[0] * invN - mean * mean;
        float rstd = rsqrtf(var + 1e-5f);
        float sc = gamma[c] * rstd;
        g_scale[c] = sc;
        g_shift[c] = beta[c] - mean * sc;
    }
}

// ---------------- normalize + transpose: [b][c][p] f32 -> [b][p][c] half -------
__global__ __launch_bounds__(256) void norm_t_k(const float* __restrict__ in) {
    const int b = blockIdx.z;
    const int c0 = blockIdx.y * 32, p0 = blockIdx.x * 32;
    const int tx = threadIdx.x & 31, ty = threadIdx.x >> 5;   // 32 x 8
    __shared__ float s[32][33];
#pragma unroll
    for (int j = 0; j < 4; j++) {
        int c = c0 + ty + j * 8;
        float v = in[((size_t)b * NC + c) * NP + p0 + tx];
        s[ty + j * 8][tx] = v * g_scale[c] + g_shift[c];
    }
    __syncthreads();
#pragma unroll
    for (int j = 0; j < 4; j++) {
        int p = p0 + ty + j * 8;
        g_xh[((size_t)b * NP + p) * NC + c0 + tx] = __float2half(s[tx][ty + j * 8]);
    }
}

// ---------------- weight prep --------------------------------------------------
// Wq/bq are pre-scaled by alpha*log2(e) so flash logits are direct exp2 args.
__global__ __launch_bounds__(256) void wprep_k(
    const float* __restrict__ Wq, const float* __restrict__ bq,
    const float* __restrict__ Wk, const float* __restrict__ bk,
    const float* __restrict__ Wv, const float* __restrict__ bv,
    const float* __restrict__ Wo)
{
    const float CE = 0.08838834764831845f * 1.4426950408889634f;
    int idx = blockIdx.x * 256 + threadIdx.x;   // 0..262143
    if (idx < 131072) {
        int o2 = idx >> 7, c = idx & 127;
        int t = o2 & 511, h = t >> 7, cp = t & 127;
        const float* W = (o2 < 512) ? Wq : Wk;
        float scale = (o2 < 512) ? CE : 1.f;
        g_wqk[idx] = __float2half(W[(cp * 4 + h) * 128 + c] * scale);
    } else if (idx < 196608) {
        int t = idx - 131072;
        int op = t >> 7, c = t & 127;
        int h = op >> 7, cp = op & 127;
        g_wv[t] = __float2half(Wv[(cp * 4 + h) * 128 + c]);
    } else {
        int t = idx - 196608;
        int o2 = t >> 9, op = t & 511;
        int h = op >> 7, cp = op & 127;
        g_wo[t] = __float2half(Wo[o2 * 512 + cp * 4 + h]);
    }
    if (idx < 512) {
        int h = idx >> 7, cp = idx & 127;
        g_bqk[idx] = bq[cp * 4 + h] * CE;
        g_bvv[idx] = bv[cp * 4 + h];
    } else if (idx < 1024) {
        int t = idx - 512, h = t >> 7, cp = t & 127;
        g_bqk[idx] = bk[cp * 4 + h];
    }
}

// ---------------- launch ------------------------------------------------------
extern "C" void kernel_launch(void* const* d_in, const int* in_sizes, int n_in,
                              void* d_out, int out_size) {
    const float* input = (const float*)d_in[0];
    const float* gamma = (const float*)d_in[1];
    const float* beta  = (const float*)d_in[2];
    const float* Wq    = (const float*)d_in[3];
    const float* bq    = (const float*)d_in[4];
    const float* Wk    = (const float*)d_in[5];
    const float* bk    = (const float*)d_in[6];
    const float* Wv    = (const float*)d_in[7];
    const float* bv    = (const float*)d_in[8];
    const float* Wo    = (const float*)d_in[9];
    const float* bo    = (const float*)d_in[10];
    float* out = (float*)d_out;

    __half *pxh, *pwqk, *pwv, *pwo, *pqkh, *pvh, *path;
    float *pbqk, *pbvv;
    cudaGetSymbolAddress((void**)&pxh,  g_xh);
    cudaGetSymbolAddress((void**)&pwqk, g_wqk);
    cudaGetSymbolAddress((void**)&pwv,  g_wv);
    cudaGetSymbolAddress((void**)&pwo,  g_wo);
    cudaGetSymbolAddress((void**)&pbqk, g_bqk);
    cudaGetSymbolAddress((void**)&pbvv, g_bvv);
    cudaGetSymbolAddress((void**)&pqkh, g_qkh);
    cudaGetSymbolAddress((void**)&pvh,  g_vh);
    cudaGetSymbolAddress((void**)&path, g_ath);

    cudaFuncSetAttribute(hgemm_nt<__half, 1>, cudaFuncAttributeMaxDynamicSharedMemorySize, 2 * BUF_BYTES);
    cudaFuncSetAttribute(hgemm_nt<__half, 2>, cudaFuncAttributeMaxDynamicSharedMemorySize, 2 * BUF_BYTES);
    cudaFuncSetAttribute(hgemm_nt<float,  4>, cudaFuncAttributeMaxDynamicSharedMemorySize, 2 * BUF_BYTES);
    cudaFuncSetAttribute(flash_k, cudaFuncAttributeMaxDynamicSharedMemorySize, FSMEM);

    // 1) batchnorm stats, normalize+transpose, weight prep
    bn_stats_k<<<NC, 256>>>(input, gamma, beta);
    wprep_k<<<1024, 256>>>(Wq, bq, Wk, bk, Wv, bv, Wo);
    norm_t_k<<<dim3(NP / 32, NC / 32, NB), 256>>>(input);

    // 2) Q|K projection: C[b][p][o''] = xh[b][p][c] * Wqk[o''][c]^T + bqk[o'']
    hgemm_nt<__half, 1><<<dim3(8, 16, NB), 256, BUF_BYTES>>>(
        pxh, pwqk, pqkh, pbqk, nullptr,
        1, NC, NC, 1024,
        (long)NP * NC, 0, 0, 0, (long)NP * 1024, 0, 1, 1.f);

    // 3) V projection: C[b][o'][p] = Wv[o'][c] * xh[b][p][c]^T + bv[o']
    hgemm_nt<__half, 2><<<dim3(16, 4, NB), 256, BUF_BYTES>>>(
        pwv, pxh, pvh, pbvv, nullptr,
        1, NC, NC, NP,
        0, 0, (long)NP * NC, 0, (long)NCH * NP, 0, 1, 1.f);

    // 4) fused attention: S -> softmax -> P V, att[b][p][(h,c')]
    flash_k<<<dim3(NP / 64, NZ), 128, FSMEM>>>();

    // 5) out = Wo' att + bo + input : M=128 N=2048 K=512 per batch
    hgemm_nt<float, 4><<<dim3(16, 1, NB), 256, 2 * BUF_BYTES>>>(
        pwo, path, out, bo, input,
        4, NCH, NCH, NP,
        0, 0, (long)NP * NCH, 0, (long)NC * NP, 0, 1, 1.f);
}

// round 9
// speedup vs baseline: 1.0341x; 1.0341x over previous
#include <cuda_runtime.h>
#include <cuda_fp16.h>
#include <cstdint>
#include <math.h>

// Problem constants
constexpr int NB  = 8;     // batch
constexpr int NC  = 128;   // channels
constexpr int NP  = 2048;  // points
constexpr int NH  = 4;     // heads
constexpr int NCH = 512;   // c*h
constexpr int NZ  = NB * NH;  // 32 (b,h) slices

// ---------------- scratch (static device globals; no allocation) -------------
__device__ __align__(1024) float  g_scale[NC];
__device__ __align__(1024) float  g_shift[NC];
__device__ __align__(1024) __half g_xh [NB * NP * NC];         // x half [b][p][c]
__device__ __align__(1024) __half g_wqk[1024 * 128];           // [(q|k)(h,c')][c]
__device__ __align__(1024) __half g_wv [512 * 128];            // [(h,c')][c]
__device__ __align__(1024) __half g_wo [128 * 512];            // [c][(h,c')]
__device__ __align__(1024) float  g_bqk[1024];
__device__ __align__(1024) float  g_bvv[512];
__device__ __align__(1024) __half g_qkh[NB * NP * 1024];       // [b][p][q(h,c')|k(h,c')]
__device__ __align__(1024) __half g_vh [NB * NCH * NP];        // [b][(h,c')][p]
__device__ __align__(1024) __half g_ath[NB * NP * NCH];        // [b][p][(h,c')]

// =================== PTX helpers =============================================
__device__ __forceinline__ uint32_t smem_u32(const void* p) {
    uint32_t a;
    asm("{ .reg .u64 t; cvta.to.shared.u64 t, %1; cvt.u32.u64 %0, t; }" : "=r"(a) : "l"(p));
    return a;
}
__device__ __forceinline__ void cp16(uint32_t s, const void* g) {
    asm volatile("cp.async.cg.shared.global [%0], [%1], 16;" :: "r"(s), "l"(g));
}
__device__ __forceinline__ void cp_commit() { asm volatile("cp.async.commit_group;"); }
__device__ __forceinline__ void cp_wait0()  { asm volatile("cp.async.wait_group 0;"); }
__device__ __forceinline__ void cp_wait1()  { asm volatile("cp.async.wait_group 1;"); }
__device__ __forceinline__ void ldsm4(uint32_t* r, uint32_t addr) {
    asm volatile("ldmatrix.sync.aligned.m8n8.x4.shared.b16 {%0,%1,%2,%3}, [%4];"
                 : "=r"(r[0]), "=r"(r[1]), "=r"(r[2]), "=r"(r[3]) : "r"(addr));
}
__device__ __forceinline__ void mma16816(float* d, const uint32_t* a, const uint32_t* b) {
    asm volatile(
        "mma.sync.aligned.m16n8k16.row.col.f32.f16.f16.f32 "
        "{%0,%1,%2,%3}, {%4,%5,%6,%7}, {%8,%9}, {%0,%1,%2,%3};"
        : "+f"(d[0]), "+f"(d[1]), "+f"(d[2]), "+f"(d[3])
        : "r"(a[0]), "r"(a[1]), "r"(a[2]), "r"(a[3]), "r"(b[0]), "r"(b[1]));
}
__device__ __forceinline__ float ex2(float x) {
    float y;
    asm("ex2.approx.f32 %0, %1;" : "=f"(y) : "f"(x));
    return y;
}

// ---------------- HMMA GEMM: C[M][N] = alpha * A[M][K] * B[N][K]^T -----------
// CTA tile 128x128, 8 warps of 32x64, K in chunks of 128, double-buffered.
// EPI: 0 = alpha only; 1 = + bias[n]; 2 = + bias[m]; 3 = plain; 4 = + bias[m] + res
constexpr int LDS_H       = 136;                  // halves per smem row (pad 8)
constexpr int TILE_HALVES = 128 * LDS_H;
constexpr int BUF_BYTES   = 2 * TILE_HALVES * 2;  // A+B one buffer = 69632 B

template <typename OutT, int EPI>
__global__ __launch_bounds__(256) void hgemm_nt(
    const __half* __restrict__ A, const __half* __restrict__ B, OutT* __restrict__ C,
    const float* __restrict__ bias, const float* __restrict__ res,
    int kchunks, int lda, int ldb, int ldc,
    long sAo, long sAi, long sBo, long sBi, long sCo, long sCi,
    int zH, float alpha)
{
    extern __shared__ __half smh[];
    const uint32_t sbase = smem_u32(smh);

    const int z  = blockIdx.z;
    const int zo = z / zH, zi = z % zH;
    const int m0 = blockIdx.y * 128, n0 = blockIdx.x * 128;
    A += (size_t)zo * sAo + (size_t)zi * sAi + (size_t)m0 * lda;
    B += (size_t)zo * sBo + (size_t)zi * sBi + (size_t)n0 * ldb;
    const size_t coff = (size_t)zo * sCo + (size_t)zi * sCi + (size_t)m0 * ldc + n0;
    C += coff;
    const float* R = res;
    if (EPI == 4) R += coff;

    const int tid  = threadIdx.x;
    const int lane = tid & 31;
    const int wid  = tid >> 5;
    const int wm   = (wid & 3) * 32;    // warp m offset
    const int wn   = (wid >> 2) * 64;   // warp n offset

    auto loadc = [&](int buf, int kofs) {
        const uint32_t ab = sbase + (uint32_t)buf * BUF_BYTES;
        const uint32_t bb = ab + TILE_HALVES * 2;
#pragma unroll
        for (int i = 0; i < 8; i++) {
            int idx = i * 256 + tid;
            int row = idx >> 4;
            int col = (idx & 15) * 8;     // halves
            cp16(ab + (uint32_t)(row * LDS_H + col) * 2, A + (size_t)row * lda + kofs + col);
            cp16(bb + (uint32_t)(row * LDS_H + col) * 2, B + (size_t)row * ldb + kofs + col);
        }
        cp_commit();
    };

    float acc[2][8][4] = {};

    loadc(0, 0);
    for (int kc = 0; kc < kchunks; kc++) {
        if (kc + 1 < kchunks) { loadc((kc + 1) & 1, (kc + 1) * 128); cp_wait1(); }
        else                  { cp_wait0(); }
        __syncthreads();

        const uint32_t ab = sbase + (uint32_t)(kc & 1) * BUF_BYTES;
        const uint32_t bb = ab + TILE_HALVES * 2;

#pragma unroll
        for (int ks = 0; ks < 8; ks++) {
            const int k0 = ks * 16;
            uint32_t af[2][4];
#pragma unroll
            for (int mf = 0; mf < 2; mf++) {
                int m  = wm + mf * 16 + (lane & 7) + ((lane >> 3) & 1) * 8;
                int kk = k0 + (lane >> 4) * 8;
                ldsm4(af[mf], ab + (uint32_t)(m * LDS_H + kk) * 2);
            }
            uint32_t bf[8][2];
#pragma unroll
            for (int p = 0; p < 4; p++) {
                int nrow = wn + p * 16 + ((lane >> 4) & 1) * 8 + (lane & 7);
                int kk   = k0 + ((lane >> 3) & 1) * 8;
                uint32_t r[4];
                ldsm4(r, bb + (uint32_t)(nrow * LDS_H + kk) * 2);
                bf[2 * p][0] = r[0]; bf[2 * p][1] = r[1];
                bf[2 * p + 1][0] = r[2]; bf[2 * p + 1][1] = r[3];
            }
#pragma unroll
            for (int mf = 0; mf < 2; mf++)
#pragma unroll
                for (int nf = 0; nf < 8; nf++)
                    mma16816(acc[mf][nf], af[mf], bf[nf]);
        }
        __syncthreads();
    }

    // epilogue: m16n8 c-frag: rows (lane>>2, +8), cols (lane&3)*2
#pragma unroll
    for (int mf = 0; mf < 2; mf++) {
#pragma unroll
        for (int nf = 0; nf < 8; nf++) {
            int m = wm + mf * 16 + (lane >> 2);
            int n = wn + nf * 8 + (lane & 3) * 2;
            float v0 = acc[mf][nf][0] * alpha, v1 = acc[mf][nf][1] * alpha;
            float v2 = acc[mf][nf][2] * alpha, v3 = acc[mf][nf][3] * alpha;
            if (EPI == 1) {
                float b0 = bias[n0 + n], b1 = bias[n0 + n + 1];
                v0 += b0; v1 += b1; v2 += b0; v3 += b1;
            }
            if (EPI == 2 || EPI == 4) {
                float bm0 = bias[m0 + m], bm1 = bias[m0 + m + 8];
                v0 += bm0; v1 += bm0; v2 += bm1; v3 += bm1;
            }
            if (EPI == 4) {
                float2 r0 = *(const float2*)(R + (size_t)m * ldc + n);
                float2 r1 = *(const float2*)(R + (size_t)(m + 8) * ldc + n);
                v0 += r0.x; v1 += r0.y; v2 += r1.x; v3 += r1.y;
            }
            if (sizeof(OutT) == 2) {
                *(__half2*)((__half*)C + (size_t)m * ldc + n)       = __floats2half2_rn(v0, v1);
                *(__half2*)((__half*)C + (size_t)(m + 8) * ldc + n) = __floats2half2_rn(v2, v3);
            } else {
                *(float2*)((float*)C + (size_t)m * ldc + n)       = make_float2(v0, v1);
                *(float2*)((float*)C + (size_t)(m + 8) * ldc + n) = make_float2(v2, v3);
            }
        }
    }
}

// ---------------- fused flash attention (no-max softmax, interleaved exp) ------
// 256 threads / 8 warps, 128-row i-tile, double-buffered K/V (R6 shape).
// exp/pack for nf-pair ks is computed immediately before its O-phase MMAs, so
// MUFU issue overlaps tensor execution of the previous ks step within one warp.
// Q is pre-scaled by alpha*log2(e), so p = exp2(S) directly.
constexpr int FTILE = 128 * LDS_H;            // halves per tile
constexpr int FSMEM = 5 * FTILE * 2;          // Q + 2x(K,V) = 174080 bytes

__global__ __launch_bounds__(256, 1) void flash_k() {
    extern __shared__ __half fsm[];
    const uint32_t sb = smem_u32(fsm);
    const int tid = threadIdx.x, lane = tid & 31, wid = tid >> 5;
    const int i0 = blockIdx.x * 128;
    const int z  = blockIdx.y;
    const int b  = z >> 2, h = z & 3;

    const __half* Qg = g_qkh + (size_t)b * NP * 1024 + (size_t)i0 * 1024 + h * 128;
    const __half* Kg = g_qkh + (size_t)b * NP * 1024 + 512 + h * 128;
    const __half* Vg = g_vh  + (size_t)b * NCH * NP + (size_t)h * 128 * NP;

    // Q tile -> smem (grouped with first KV commit)
#pragma unroll
    for (int i = 0; i < 8; i++) {
        int idx = i * 256 + tid, row = idx >> 4, col = (idx & 15) * 8;
        cp16(sb + (uint32_t)(row * LDS_H + col) * 2, Qg + (size_t)row * 1024 + col);
    }
    auto loadKV = [&](int buf, int j0) {
        uint32_t kb = sb + (uint32_t)(FTILE + buf * 2 * FTILE) * 2;
        uint32_t vb = kb + FTILE * 2;
#pragma unroll
        for (int i = 0; i < 8; i++) {
            int idx = i * 256 + tid, row = idx >> 4, col = (idx & 15) * 8;
            cp16(kb + (uint32_t)(row * LDS_H + col) * 2, Kg + (size_t)(j0 + row) * 1024 + col);
            cp16(vb + (uint32_t)(row * LDS_H + col) * 2, Vg + (size_t)row * NP + j0 + col);
        }
        cp_commit();
    };
    loadKV(0, 0);

    const int wm = wid * 16;
    uint32_t qf[8][4];
    float oacc[16][4] = {};
    float l0 = 0.f, l1 = 0.f;

    for (int kc = 0; kc < 16; kc++) {
        if (kc + 1 < 16) { loadKV((kc + 1) & 1, (kc + 1) * 128); cp_wait1(); }
        else             { cp_wait0(); }
        __syncthreads();
        if (kc == 0) {
#pragma unroll
            for (int ks = 0; ks < 8; ks++)
                ldsm4(qf[ks], sb + (uint32_t)((wm + (lane & 15)) * LDS_H
                                              + ks * 16 + (lane >> 4) * 8) * 2);
        }
        const uint32_t kb = sb + (uint32_t)(FTILE + (kc & 1) * 2 * FTILE) * 2;
        const uint32_t vb = kb + FTILE * 2;

        // ---- S = Q K^T (Q pre-scaled; results are exp2 args) ----
        float sacc[16][4] = {};
#pragma unroll
        for (int ks = 0; ks < 8; ks++) {
            uint32_t bf[16][2];
#pragma unroll
            for (int p = 0; p < 8; p++) {
                int nrow = p * 16 + ((lane >> 4) & 1) * 8 + (lane & 7);
                int kk   = ks * 16 + ((lane >> 3) & 1) * 8;
                uint32_t r[4];
                ldsm4(r, kb + (uint32_t)(nrow * LDS_H + kk) * 2);
                bf[2 * p][0] = r[0]; bf[2 * p][1] = r[1];
                bf[2 * p + 1][0] = r[2]; bf[2 * p + 1][1] = r[3];
            }
#pragma unroll
            for (int nf = 0; nf < 16; nf++) mma16816(sacc[nf], qf[ks], bf[nf]);
        }

        // ---- O phase with interleaved exp: per ks, exp+pack nf=2ks,2ks+1 ----
#pragma unroll
        for (int ks = 0; ks < 8; ks++) {
            // exp2 + pack for this ks's A-frag (8 values, independent of MMAs)
            float pa0 = ex2(sacc[2 * ks][0]),     pa1 = ex2(sacc[2 * ks][1]);
            float pa2 = ex2(sacc[2 * ks][2]),     pa3 = ex2(sacc[2 * ks][3]);
            float pb0 = ex2(sacc[2 * ks + 1][0]), pb1 = ex2(sacc[2 * ks + 1][1]);
            float pb2 = ex2(sacc[2 * ks + 1][2]), pb3 = ex2(sacc[2 * ks + 1][3]);
            l0 += pa0 + pa1 + pb0 + pb1;
            l1 += pa2 + pa3 + pb2 + pb3;
            __half2 hA01 = __floats2half2_rn(pa0, pa1);
            __half2 hA23 = __floats2half2_rn(pa2, pa3);
            __half2 hB01 = __floats2half2_rn(pb0, pb1);
            __half2 hB23 = __floats2half2_rn(pb2, pb3);
            uint32_t af[4];
            af[0] = *(uint32_t*)&hA01;
            af[1] = *(uint32_t*)&hA23;
            af[2] = *(uint32_t*)&hB01;
            af[3] = *(uint32_t*)&hB23;

            uint32_t bfv[16][2];
#pragma unroll
            for (int p = 0; p < 8; p++) {
                int nrow = p * 16 + ((lane >> 4) & 1) * 8 + (lane & 7);
                int kk   = ks * 16 + ((lane >> 3) & 1) * 8;
                uint32_t r[4];
                ldsm4(r, vb + (uint32_t)(nrow * LDS_H + kk) * 2);
                bfv[2 * p][0] = r[0]; bfv[2 * p][1] = r[1];
                bfv[2 * p + 1][0] = r[2]; bfv[2 * p + 1][1] = r[3];
            }
#pragma unroll
            for (int nf = 0; nf < 16; nf++) mma16816(oacc[nf], af, bfv[nf]);
        }
        __syncthreads();   // compute done before next prefetch overwrites buffer
    }

    // ---- epilogue: reduce l across quad, normalize, write att ----
    l0 += __shfl_xor_sync(0xffffffffu, l0, 1);
    l0 += __shfl_xor_sync(0xffffffffu, l0, 2);
    l1 += __shfl_xor_sync(0xffffffffu, l1, 1);
    l1 += __shfl_xor_sync(0xffffffffu, l1, 2);
    float inv0 = 1.f / l0, inv1 = 1.f / l1;
    const int row0 = i0 + wm + (lane >> 2);
    __half* ob = g_ath + (size_t)b * NP * NCH;
#pragma unroll
    for (int nf = 0; nf < 16; nf++) {
        int col = h * 128 + nf * 8 + (lane & 3) * 2;
        *(__half2*)(ob + (size_t)row0 * NCH + col) =
            __floats2half2_rn(oacc[nf][0] * inv0, oacc[nf][1] * inv0);
        *(__half2*)(ob + (size_t)(row0 + 8) * NCH + col) =
            __floats2half2_rn(oacc[nf][2] * inv1, oacc[nf][3] * inv1);
    }
}

// ---------------- batchnorm statistics ---------------------------------------
__global__ __launch_bounds__(256) void bn_stats_k(const float* __restrict__ in,
                                                  const float* __restrict__ gamma,
                                                  const float* __restrict__ beta) {
    const int c = blockIdx.x;
    const int t = threadIdx.x;
    float s = 0.f, ss = 0.f;
    for (int idx = t; idx < NB * NP; idx += 256) {
        int b = idx >> 11;
        int p = idx & (NP - 1);
        float v = in[(size_t)b * NC * NP + (size_t)c * NP + p];
        s += v; ss += v * v;
    }
    __shared__ float r1[256], r2[256];
    r1[t] = s; r2[t] = ss;
    __syncthreads();
    for (int off = 128; off > 0; off >>= 1) {
        if (t < off) { r1[t] += r1[t + off]; r2[t] += r2[t + off]; }
        __syncthreads();
    }
    if (t == 0) {
        const float invN = 1.f / (NB * NP);
        float mean = r1[0] * invN;
        float var  = r2[0] * invN - mean * mean;
        float rstd = rsqrtf(var + 1e-5f);
        float sc = gamma[c] * rstd;
        g_scale[c] = sc;
        g_shift[c] = beta[c] - mean * sc;
    }
}

// ---------------- normalize + transpose: [b][c][p] f32 -> [b][p][c] half -------
__global__ __launch_bounds__(256) void norm_t_k(const float* __restrict__ in) {
    const int b = blockIdx.z;
    const int c0 = blockIdx.y * 32, p0 = blockIdx.x * 32;
    const int tx = threadIdx.x & 31, ty = threadIdx.x >> 5;   // 32 x 8
    __shared__ float s[32][33];
#pragma unroll
    for (int j = 0; j < 4; j++) {
        int c = c0 + ty + j * 8;
        float v = in[((size_t)b * NC + c) * NP + p0 + tx];
        s[ty + j * 8][tx] = v * g_scale[c] + g_shift[c];
    }
    __syncthreads();
#pragma unroll
    for (int j = 0; j < 4; j++) {
        int p = p0 + ty + j * 8;
        g_xh[((size_t)b * NP + p) * NC + c0 + tx] = __float2half(s[tx][ty + j * 8]);
    }
}

// ---------------- weight prep --------------------------------------------------
// Wq/bq are pre-scaled by alpha*log2(e) so flash logits are direct exp2 args.
__global__ __launch_bounds__(256) void wprep_k(
    const float* __restrict__ Wq, const float* __restrict__ bq,
    const float* __restrict__ Wk, const float* __restrict__ bk,
    const float* __restrict__ Wv, const float* __restrict__ bv,
    const float* __restrict__ Wo)
{
    const float CE = 0.08838834764831845f * 1.4426950408889634f;
    int idx = blockIdx.x * 256 + threadIdx.x;   // 0..262143
    if (idx < 131072) {
        int o2 = idx >> 7, c = idx & 127;
        int t = o2 & 511, h = t >> 7, cp = t & 127;
        const float* W = (o2 < 512) ? Wq : Wk;
        float scale = (o2 < 512) ? CE : 1.f;
        g_wqk[idx] = __float2half(W[(cp * 4 + h) * 128 + c] * scale);
    } else if (idx < 196608) {
        int t = idx - 131072;
        int op = t >> 7, c = t & 127;
        int h = op >> 7, cp = op & 127;
        g_wv[t] = __float2half(Wv[(cp * 4 + h) * 128 + c]);
    } else {
        int t = idx - 196608;
        int o2 = t >> 9, op = t & 511;
        int h = op >> 7, cp = op & 127;
        g_wo[t] = __float2half(Wo[o2 * 512 + cp * 4 + h]);
    }
    if (idx < 512) {
        int h = idx >> 7, cp = idx & 127;
        g_bqk[idx] = bq[cp * 4 + h] * CE;
        g_bvv[idx] = bv[cp * 4 + h];
    } else if (idx < 1024) {
        int t = idx - 512, h = t >> 7, cp = t & 127;
        g_bqk[idx] = bk[cp * 4 + h];
    }
}

// ---------------- launch ------------------------------------------------------
extern "C" void kernel_launch(void* const* d_in, const int* in_sizes, int n_in,
                              void* d_out, int out_size) {
    const float* input = (const float*)d_in[0];
    const float* gamma = (const float*)d_in[1];
    const float* beta  = (const float*)d_in[2];
    const float* Wq    = (const float*)d_in[3];
    const float* bq    = (const float*)d_in[4];
    const float* Wk    = (const float*)d_in[5];
    const float* bk    = (const float*)d_in[6];
    const float* Wv    = (const float*)d_in[7];
    const float* bv    = (const float*)d_in[8];
    const float* Wo    = (const float*)d_in[9];
    const float* bo    = (const float*)d_in[10];
    float* out = (float*)d_out;

    __half *pxh, *pwqk, *pwv, *pwo, *pqkh, *pvh, *path;
    float *pbqk, *pbvv;
    cudaGetSymbolAddress((void**)&pxh,  g_xh);
    cudaGetSymbolAddress((void**)&pwqk, g_wqk);
    cudaGetSymbolAddress((void**)&pwv,  g_wv);
    cudaGetSymbolAddress((void**)&pwo,  g_wo);
    cudaGetSymbolAddress((void**)&pbqk, g_bqk);
    cudaGetSymbolAddress((void**)&pbvv, g_bvv);
    cudaGetSymbolAddress((void**)&pqkh, g_qkh);
    cudaGetSymbolAddress((void**)&pvh,  g_vh);
    cudaGetSymbolAddress((void**)&path, g_ath);

    cudaFuncSetAttribute(hgemm_nt<__half, 1>, cudaFuncAttributeMaxDynamicSharedMemorySize, 2 * BUF_BYTES);
    cudaFuncSetAttribute(hgemm_nt<__half, 2>, cudaFuncAttributeMaxDynamicSharedMemorySize, 2 * BUF_BYTES);
    cudaFuncSetAttribute(hgemm_nt<float,  4>, cudaFuncAttributeMaxDynamicSharedMemorySize, 2 * BUF_BYTES);
    cudaFuncSetAttribute(flash_k, cudaFuncAttributeMaxDynamicSharedMemorySize, FSMEM);

    // 1) batchnorm stats, normalize+transpose, weight prep
    bn_stats_k<<<NC, 256>>>(input, gamma, beta);
    wprep_k<<<1024, 256>>>(Wq, bq, Wk, bk, Wv, bv, Wo);
    norm_t_k<<<dim3(NP / 32, NC / 32, NB), 256>>>(input);

    // 2) Q|K projection: C[b][p][o''] = xh[b][p][c] * Wqk[o''][c]^T + bqk[o'']
    hgemm_nt<__half, 1><<<dim3(8, 16, NB), 256, BUF_BYTES>>>(
        pxh, pwqk, pqkh, pbqk, nullptr,
        1, NC, NC, 1024,
        (long)NP * NC, 0, 0, 0, (long)NP * 1024, 0, 1, 1.f);

    // 3) V projection: C[b][o'][p] = Wv[o'][c] * xh[b][p][c]^T + bv[o']
    hgemm_nt<__half, 2><<<dim3(16, 4, NB), 256, BUF_BYTES>>>(
        pwv, pxh, pvh, pbvv, nullptr,
        1, NC, NC, NP,
        0, 0, (long)NP * NC, 0, (long)NCH * NP, 0, 1, 1.f);

    // 4) fused attention: S -> softmax -> P V, att[b][p][(h,c')]
    flash_k<<<dim3(NP / 128, NZ), 256, FSMEM>>>();

    // 5) out = Wo' att + bo + input : M=128 N=2048 K=512 per batch
    hgemm_nt<float, 4><<<dim3(16, 1, NB), 256, 2 * BUF_BYTES>>>(
        pwo, path, out, bo, input,
        4, NCH, NCH, NP,
        0, 0, (long)NP * NCH, 0, (long)NC * NP, 0, 1, 1.f);
}